// round 1
// baseline (speedup 1.0000x reference)
#include <cuda_runtime.h>
#include <cstdint>

// Problem constants
#define NROWS_MAX 131072
#define DIM 512
#define NSTEP 50

__device__ float g_loss_accum;

__device__ __forceinline__ float sqrt_approx(float x) {
    float y; asm("sqrt.approx.f32 %0, %1;" : "=f"(y) : "f"(x)); return y;
}
__device__ __forceinline__ float rcp_approx(float x) {
    float y; asm("rcp.approx.f32 %0, %1;" : "=f"(y) : "f"(x)); return y;
}

__global__ void wm_zero_kernel() { g_loss_accum = 0.0f; }

__global__ __launch_bounds__(128) void wm_kernel(
    const float* __restrict__ mu_in,
    const float* __restrict__ logvar_in,
    const float* __restrict__ carrier,
    float* __restrict__ mu_out,
    float* __restrict__ logvar_out,
    int nrows)
{
    __shared__ float blk_loss;
    if (threadIdx.x == 0) blk_loss = 0.0f;
    __syncthreads();

    const int warp = (blockIdx.x * blockDim.x + threadIdx.x) >> 5;
    const int lane = threadIdx.x & 31;

    const float B1 = 0.9f;
    const float B2 = 0.999f;
    const float C1 = 1.0f - B1;          // matches reference fp32 arithmetic
    const float C2 = 1.0f - B2;
    const float LR = 0.01f;
    const float EPS = 1e-8f;
    const float S = 1.0f / 131072.0f;    // 2^-17, exact (lambda_w = 1, mean over B)

    float mu[16], c[16], m[16], v[16];

    if (warp < nrows) {
        const float4* mrow = (const float4*)(mu_in + (size_t)warp * DIM);
        const float4* crow = (const float4*)carrier;
        const float4* lrow = (const float4*)(logvar_in + (size_t)warp * DIM);
        float4*       lout = (float4*)(logvar_out + (size_t)warp * DIM);

#pragma unroll
        for (int i = 0; i < 4; i++) {
            float4 a = mrow[lane + 32 * i];
            mu[4 * i + 0] = a.x; mu[4 * i + 1] = a.y;
            mu[4 * i + 2] = a.z; mu[4 * i + 3] = a.w;
            float4 b = crow[lane + 32 * i];
            c[4 * i + 0] = b.x; c[4 * i + 1] = b.y;
            c[4 * i + 2] = b.z; c[4 * i + 3] = b.w;
            // log_var passthrough fused here (hidden under compute)
            lout[lane + 32 * i] = lrow[lane + 32 * i];
        }
#pragma unroll
        for (int i = 0; i < 16; i++) { m[i] = 0.0f; v[i] = 0.0f; }

        float b1t = 1.0f, b2t = 1.0f;
        float loss_val = 0.0f;

#pragma unroll 1
        for (int t = 1; t <= NSTEP; ++t) {
            // dot = mu . carrier ; nn = ||mu||^2  (warp reduction)
            float dp = 0.0f, np = 0.0f;
#pragma unroll
            for (int i = 0; i < 16; i++) {
                dp = fmaf(mu[i], c[i], dp);
                np = fmaf(mu[i], mu[i], np);
            }
#pragma unroll
            for (int off = 16; off; off >>= 1) {
                dp += __shfl_xor_sync(0xffffffffu, dp, off);
                np += __shfl_xor_sync(0xffffffffu, np, off);
            }

            const float norm = sqrt_approx(np);
            // COS_THETA == 1.0f (fp32 betainc bisection converges to the fp32
            // rounding boundary 1 - 2^-25; sqrt -> rounds to 1.0f). Margin >= 0
            // always by Cauchy-Schwarz, but keep the predicate for exactness.
            const float margin = norm - dp;
            if (t == NSTEP) loss_val = fmaxf(margin, 0.0f);
            const bool active = margin > 0.0f;
            const float rnorm = norm * rcp_approx(np);  // 1/norm = norm/nn

            // per-step scalars (rescaled Adam):
            //   m' = m_true / (C1*S), v' = v_true / (C2*S^2)
            //   upd = A_t * m' / (sqrt(v') + E_t)
            //   ds  = sqrt(C2 / (1 - B2^t))
            //   A_t = LR*C1 / ((1 - B1^t) * ds),  E_t = EPS / (S * ds)
            b1t *= B1;
            b2t *= B2;
            const float ds = sqrt_approx(C2 * rcp_approx(1.0f - b2t));
            const float A  = LR * C1 * rcp_approx((1.0f - b1t) * ds);
            const float E  = (EPS / S) * rcp_approx(ds);

#pragma unroll
            for (int i = 0; i < 16; i++) {
                float G = active ? fmaf(rnorm, mu[i], -c[i]) : 0.0f;
                m[i] = fmaf(B1, m[i], G);
                v[i] = fmaf(B2, v[i], G * G);
                float s = sqrt_approx(v[i]);
                float w = (A * m[i]) * rcp_approx(s + E);
                mu[i] -= w;
            }
        }

        float4* orow = (float4*)(mu_out + (size_t)warp * DIM);
#pragma unroll
        for (int i = 0; i < 4; i++) {
            float4 a;
            a.x = mu[4 * i + 0]; a.y = mu[4 * i + 1];
            a.z = mu[4 * i + 2]; a.w = mu[4 * i + 3];
            orow[lane + 32 * i] = a;
        }

        if (lane == 0) atomicAdd(&blk_loss, loss_val);
    }

    __syncthreads();
    if (threadIdx.x == 0) atomicAdd(&g_loss_accum, blk_loss);
}

__global__ void wm_finalize_kernel(float* __restrict__ out_loss) {
    out_loss[0] = g_loss_accum * (1.0f / 131072.0f);
}

extern "C" void kernel_launch(void* const* d_in, const int* in_sizes, int n_in,
                              void* d_out, int out_size) {
    const float* mu      = (const float*)d_in[0];
    const float* log_var = (const float*)d_in[1];
    const float* carrier = (const float*)d_in[2];

    const int n_elem = in_sizes[0];          // 131072 * 512
    const int nrows  = n_elem / DIM;

    float* out        = (float*)d_out;
    float* mu_out     = out;                 // [0, n_elem)
    float* logvar_out = out + n_elem;        // [n_elem, 2*n_elem)
    float* loss_out   = out + 2 * (size_t)n_elem;  // scalar

    wm_zero_kernel<<<1, 1>>>();

    const int threads = 128;                 // 4 warps (rows) per block
    const int blocks  = (nrows * 32 + threads - 1) / threads;
    wm_kernel<<<blocks, threads>>>(mu, log_var, carrier, mu_out, logvar_out, nrows);

    wm_finalize_kernel<<<1, 1>>>(loss_out);
}

// round 2
// speedup vs baseline: 1.1718x; 1.1718x over previous
#include <cuda_runtime.h>
#include <cstdint>

#define DIM 512
#define NSTEP 50

typedef unsigned long long u64;

__device__ float g_loss_accum;

__device__ __forceinline__ float sqrt_approx(float x) {
    float y; asm("sqrt.approx.f32 %0, %1;" : "=f"(y) : "f"(x)); return y;
}
__device__ __forceinline__ float rcp_approx(float x) {
    float y; asm("rcp.approx.f32 %0, %1;" : "=f"(y) : "f"(x)); return y;
}
__device__ __forceinline__ u64 pk2(float lo, float hi) {
    u64 r; asm("mov.b64 %0, {%1,%2};" : "=l"(r) : "f"(lo), "f"(hi)); return r;
}
__device__ __forceinline__ void unpk2(float& lo, float& hi, u64 v) {
    asm("mov.b64 {%0,%1}, %2;" : "=f"(lo), "=f"(hi) : "l"(v));
}
__device__ __forceinline__ u64 pk2i(unsigned lo, unsigned hi) {
    u64 r; asm("mov.b64 %0, {%1,%2};" : "=l"(r) : "r"(lo), "r"(hi)); return r;
}
#define FMA2(d, a, b, c) asm("fma.rn.f32x2 %0, %1, %2, %3;" : "=l"(d) : "l"(a), "l"(b), "l"(c))
#define MUL2(d, a, b)    asm("mul.rn.f32x2 %0, %1, %2;"     : "=l"(d) : "l"(a), "l"(b))

__global__ void wm_zero_kernel() { g_loss_accum = 0.0f; }

__global__ __launch_bounds__(128) void wm_kernel(
    const float* __restrict__ mu_in,
    const float* __restrict__ logvar_in,
    const float* __restrict__ carrier,
    float* __restrict__ mu_out,
    float* __restrict__ logvar_out,
    int nrows)
{
    __shared__ float blk_loss;
    if (threadIdx.x == 0) blk_loss = 0.0f;
    __syncthreads();

    const int warp = (blockIdx.x * blockDim.x + threadIdx.x) >> 5;
    const int lane = threadIdx.x & 31;

    const float B1 = 0.9f;
    const float B2 = 0.999f;
    const float C1 = 1.0f - B1;
    const float C2 = 1.0f - B2;
    const float LR = 0.01f;
    const float EPS = 1e-8f;
    const float S = 1.0f / 131072.0f;   // exact 2^-17 (lambda_w=1, mean over B)

    // Packed state: 8 f32x2 pairs each = 16 floats/lane = 512/warp
    u64 mu2[8], cN2[8], m2[8], v2[8];

    if (warp < nrows) {
        const float4* mrow = (const float4*)(mu_in + (size_t)warp * DIM);
        const float4* crow = (const float4*)carrier;
        const float4* lrow = (const float4*)(logvar_in + (size_t)warp * DIM);
        float4*       lout = (float4*)(logvar_out + (size_t)warp * DIM);

#pragma unroll
        for (int i = 0; i < 4; i++) {
            float4 a = mrow[lane + 32 * i];
            mu2[2 * i]     = pk2(a.x, a.y);
            mu2[2 * i + 1] = pk2(a.z, a.w);
            float4 b = crow[lane + 32 * i];
            cN2[2 * i]     = pk2(-b.x, -b.y);   // store negated carrier
            cN2[2 * i + 1] = pk2(-b.z, -b.w);
            lout[lane + 32 * i] = lrow[lane + 32 * i];  // log_var passthrough
            m2[2 * i] = 0ull; m2[2 * i + 1] = 0ull;
            v2[2 * i] = 0ull; v2[2 * i + 1] = 0ull;
        }

        const u64 B1_2 = pk2(B1, B1);
        const u64 B2_2 = pk2(B2, B2);
        const u64 ONE2 = pk2(1.0f, 1.0f);

        float b1t = 1.0f, b2t = 1.0f;
        float loss_val = 0.0f;

#pragma unroll 1
        for (int t = 1; t <= NSTEP; ++t) {
            // dpn = -(mu.c), np = ||mu||^2  (packed accumulate, warp reduce)
            u64 dpa = 0ull, npa = 0ull;
#pragma unroll
            for (int p = 0; p < 8; p++) {
                FMA2(dpa, mu2[p], cN2[p], dpa);
                FMA2(npa, mu2[p], mu2[p], npa);
            }
            float dl, dh, nl, nh;
            unpk2(dl, dh, dpa);
            unpk2(nl, nh, npa);
            float dpn = dl + dh, np = nl + nh;
#pragma unroll
            for (int off = 16; off; off >>= 1) {
                dpn += __shfl_xor_sync(0xffffffffu, dpn, off);
                np  += __shfl_xor_sync(0xffffffffu, np,  off);
            }

            const float norm = sqrt_approx(np);
            // COS_THETA == 1.0f in fp32 (betainc bisection hits the fp32
            // rounding boundary). margin = norm - dot = norm + dpn (c negated).
            const float margin = norm + dpn;
            if (t == NSTEP) loss_val = fmaxf(margin, 0.0f);
            const bool active = margin > 0.0f;   // warp-uniform; true in practice
            const float rnorm = norm * rcp_approx(np);   // 1/||mu||

            // rescaled Adam per-step scalars (algebraically identical to ref):
            //   m' = m/(C1*S), v' = v/(C2*S^2)
            //   ds = sqrt(C2/(1-B2^t)); A = LR*C1/((1-B1^t)*ds); E = EPS/(S*ds)
            b1t *= B1;
            b2t *= B2;
            const float ds = sqrt_approx(C2 * rcp_approx(1.0f - b2t));
            const float A  = LR * C1 * rcp_approx((1.0f - b1t) * ds);
            const float E  = (EPS / S) * rcp_approx(ds);

            const u64 rn2 = pk2(rnorm, rnorm);
            const u64 nA2 = pk2(-A, -A);

            if (active) {
#pragma unroll
                for (int p = 0; p < 8; p++) {
                    u64 G;
                    FMA2(G, rn2, mu2[p], cN2[p]);          // grad/S (masked on)
                    FMA2(m2[p], B1_2, m2[p], G);            // m' = B1*m' + G
                    u64 gg; MUL2(gg, G, G);
                    FMA2(v2[p], B2_2, v2[p], gg);           // v' = B2*v' + G^2
                    float vlo, vhi; unpk2(vlo, vhi, v2[p]);
                    float slo = sqrt_approx(vlo);
                    float shi = sqrt_approx(vhi);
                    float dlo = slo + E;
                    float dhi = shi + E;
                    // packed reciprocal: int-magic seed + 2 Newton iterations
                    unsigned ilo = __float_as_uint(dlo);
                    unsigned ihi = __float_as_uint(dhi);
                    u64 y  = pk2i(0x7EF477D5u - ilo, 0x7EF477D5u - ihi);
                    u64 nd = pk2i(ilo ^ 0x80000000u, ihi ^ 0x80000000u); // -d
                    u64 tN;
                    FMA2(tN, nd, y, ONE2);                  // 1 - d*y
                    FMA2(y, y, tN, y);                      // y += y*(1-d*y)
                    FMA2(tN, nd, y, ONE2);
                    FMA2(y, y, tN, y);
                    u64 u_; MUL2(u_, m2[p], y);             // m'/(s+E)
                    FMA2(mu2[p], nA2, u_, mu2[p]);          // mu -= A * u
                }
            } else {
                // inactive hinge: G = 0 (kept for exactness; never taken here)
#pragma unroll
                for (int p = 0; p < 8; p++) {
                    u64 Z = 0ull;
                    FMA2(m2[p], B1_2, m2[p], Z);
                    FMA2(v2[p], B2_2, v2[p], Z);
                    float vlo, vhi; unpk2(vlo, vhi, v2[p]);
                    float slo = sqrt_approx(vlo);
                    float shi = sqrt_approx(vhi);
                    float dlo = slo + E;
                    float dhi = shi + E;
                    unsigned ilo = __float_as_uint(dlo);
                    unsigned ihi = __float_as_uint(dhi);
                    u64 y  = pk2i(0x7EF477D5u - ilo, 0x7EF477D5u - ihi);
                    u64 nd = pk2i(ilo ^ 0x80000000u, ihi ^ 0x80000000u);
                    u64 tN;
                    FMA2(tN, nd, y, ONE2);
                    FMA2(y, y, tN, y);
                    FMA2(tN, nd, y, ONE2);
                    FMA2(y, y, tN, y);
                    u64 u_; MUL2(u_, m2[p], y);
                    FMA2(mu2[p], nA2, u_, mu2[p]);
                }
            }
        }

        float4* orow = (float4*)(mu_out + (size_t)warp * DIM);
#pragma unroll
        for (int i = 0; i < 4; i++) {
            float4 a;
            unpk2(a.x, a.y, mu2[2 * i]);
            unpk2(a.z, a.w, mu2[2 * i + 1]);
            orow[lane + 32 * i] = a;
        }

        if (lane == 0) atomicAdd(&blk_loss, loss_val);
    }

    __syncthreads();
    if (threadIdx.x == 0) atomicAdd(&g_loss_accum, blk_loss);
}

__global__ void wm_finalize_kernel(float* __restrict__ out_loss) {
    out_loss[0] = g_loss_accum * (1.0f / 131072.0f);
}

extern "C" void kernel_launch(void* const* d_in, const int* in_sizes, int n_in,
                              void* d_out, int out_size) {
    const float* mu      = (const float*)d_in[0];
    const float* log_var = (const float*)d_in[1];
    const float* carrier = (const float*)d_in[2];

    const int n_elem = in_sizes[0];          // 131072 * 512
    const int nrows  = n_elem / DIM;

    float* out        = (float*)d_out;
    float* mu_out     = out;
    float* logvar_out = out + n_elem;
    float* loss_out   = out + 2 * (size_t)n_elem;

    wm_zero_kernel<<<1, 1>>>();

    const int threads = 128;                 // 4 warps (rows) per block
    const int blocks  = (nrows * 32 + threads - 1) / threads;
    wm_kernel<<<blocks, threads>>>(mu, log_var, carrier, mu_out, logvar_out, nrows);

    wm_finalize_kernel<<<1, 1>>>(loss_out);
}

// round 4
// speedup vs baseline: 1.2817x; 1.0938x over previous
#include <cuda_runtime.h>
#include <cstdint>

#define DIM 512
#define NSTEP 50

typedef unsigned long long u64;

__device__ float g_loss_accum;
__device__ float2 g_ae[NSTEP + 1];   // per-step {A_t, E_t}

__device__ __forceinline__ float sqrt_approx(float x) {
    float y; asm("sqrt.approx.f32 %0, %1;" : "=f"(y) : "f"(x)); return y;
}
__device__ __forceinline__ float rcp_approx(float x) {
    float y; asm("rcp.approx.f32 %0, %1;" : "=f"(y) : "f"(x)); return y;
}
__device__ __forceinline__ u64 pk2(float lo, float hi) {
    u64 r; asm("mov.b64 %0, {%1,%2};" : "=l"(r) : "f"(lo), "f"(hi)); return r;
}
__device__ __forceinline__ void unpk2(float& lo, float& hi, u64 v) {
    asm("mov.b64 {%0,%1}, %2;" : "=f"(lo), "=f"(hi) : "l"(v));
}
__device__ __forceinline__ u64 pk2i(unsigned lo, unsigned hi) {
    u64 r; asm("mov.b64 %0, {%1,%2};" : "=l"(r) : "r"(lo), "r"(hi)); return r;
}
#define FMA2(d, a, b, c) asm("fma.rn.f32x2 %0, %1, %2, %3;" : "=l"(d) : "l"(a), "l"(b), "l"(c))
#define MUL2(d, a, b)    asm("mul.rn.f32x2 %0, %1, %2;"     : "=l"(d) : "l"(a), "l"(b))

// Init: zero loss accumulator; precompute per-step Adam scalars (fp64).
//   rescaled Adam: m' = m/(C1*S), v' = v/(C2*S^2), S = 1/B
//   ds = sqrt(C2/(1-B2^t)); A_t = LR*C1/((1-B1^t)*ds); E_t = (EPS/S)/ds
__global__ void wm_init_kernel() {
    g_loss_accum = 0.0f;
    double b1t = 1.0, b2t = 1.0;
    for (int t = 1; t <= NSTEP; ++t) {
        b1t *= 0.9;
        b2t *= 0.999;
        double ds = sqrt(0.001 / (1.0 - b2t));
        double A  = 0.01 * 0.1 / ((1.0 - b1t) * ds);
        double E  = (1e-8 * 131072.0) / ds;
        g_ae[t] = make_float2((float)A, (float)E);
    }
}

__global__ __launch_bounds__(128) void wm_kernel(
    const float* __restrict__ mu_in,
    const float* __restrict__ logvar_in,
    const float* __restrict__ carrier,
    float* __restrict__ mu_out,
    float* __restrict__ logvar_out,
    int nrows)
{
    __shared__ float blk_loss;
    if (threadIdx.x == 0) blk_loss = 0.0f;
    __syncthreads();

    const int warp = (blockIdx.x * blockDim.x + threadIdx.x) >> 5;
    const int lane = threadIdx.x & 31;

    const float B1 = 0.9f;
    const float B2 = 0.999f;

    // Packed state: 8 f32x2 pairs each = 16 floats/lane = 512/warp
    u64 mu2[8], cN2[8], m2[8], v2[8];

    if (warp < nrows) {
        const float4* mrow = (const float4*)(mu_in + (size_t)warp * DIM);
        const float4* crow = (const float4*)carrier;
        const float4* lrow = (const float4*)(logvar_in + (size_t)warp * DIM);
        float4*       lout = (float4*)(logvar_out + (size_t)warp * DIM);

#pragma unroll
        for (int i = 0; i < 4; i++) {
            float4 a = mrow[lane + 32 * i];
            mu2[2 * i]     = pk2(a.x, a.y);
            mu2[2 * i + 1] = pk2(a.z, a.w);
            float4 b = crow[lane + 32 * i];
            cN2[2 * i]     = pk2(-b.x, -b.y);   // store negated carrier
            cN2[2 * i + 1] = pk2(-b.z, -b.w);
            lout[lane + 32 * i] = lrow[lane + 32 * i];  // log_var passthrough
            m2[2 * i] = 0ull; m2[2 * i + 1] = 0ull;
            v2[2 * i] = 0ull; v2[2 * i + 1] = 0ull;
        }

        const u64 B1_2 = pk2(B1, B1);
        const u64 B2_2 = pk2(B2, B2);
        const u64 ONE2 = pk2(1.0f, 1.0f);

        float loss_val = 0.0f;

#pragma unroll 1
        for (int t = 1; t <= NSTEP; ++t) {
            // hoisted early: 200+ cycles of slack before first use
            const float2 ae = g_ae[t];
            const float A = ae.x, E = ae.y;
            const float nE = -E;

            // dpn = -(mu.c), np = ||mu||^2  (packed accumulate, warp reduce)
            u64 dpa = 0ull, npa = 0ull;
#pragma unroll
            for (int p = 0; p < 8; p++) {
                FMA2(dpa, mu2[p], cN2[p], dpa);
                FMA2(npa, mu2[p], mu2[p], npa);
            }
            float dl, dh, nl, nh;
            unpk2(dl, dh, dpa);
            unpk2(nl, nh, npa);
            float dpn = dl + dh, np = nl + nh;
#pragma unroll
            for (int off = 16; off; off >>= 1) {
                dpn += __shfl_xor_sync(0xffffffffu, dpn, off);
                np  += __shfl_xor_sync(0xffffffffu, np,  off);
            }

            const float norm = sqrt_approx(np);
            // COS_THETA == 1.0f in fp32; margin = norm - dot = norm + dpn.
            const float margin = norm + dpn;
            if (t == NSTEP) loss_val = fmaxf(margin, 0.0f);
            const bool active = margin > 0.0f;   // warp-uniform
            const float rnorm = norm * rcp_approx(np);   // 1/||mu||

            const u64 rn2 = pk2(rnorm, rnorm);
            const u64 nA2 = pk2(-A, -A);

            if (active) {
#pragma unroll
                for (int p = 0; p < 8; p++) {
                    u64 G;
                    FMA2(G, rn2, mu2[p], cN2[p]);           // G = mu/||mu|| - c
                    FMA2(m2[p], B1_2, m2[p], G);             // m' = B1*m' + G
                    u64 gg; MUL2(gg, G, G);
                    FMA2(v2[p], B2_2, v2[p], gg);            // v' = B2*v' + G^2
                    float vlo, vhi; unpk2(vlo, vhi, v2[p]);
                    // nd = -(sqrt(v)+E) in ONE fadd; magic seed for 1/d from
                    // bits(nd): bits(-d) = 0x80000000 + bits(d), so
                    // 0x7EF477D5 - bits(d) == 0xFEF477D5 - bits(nd).
                    float ndlo = nE - sqrt_approx(vlo);
                    float ndhi = nE - sqrt_approx(vhi);
                    u64 y = pk2i(0xFEF477D5u - __float_as_uint(ndlo),
                                 0xFEF477D5u - __float_as_uint(ndhi));
                    u64 nd = pk2(ndlo, ndhi);
                    u64 tN;
                    // TWO Newton steps: one leaves a biased ~1.4e-3 error that
                    // compounds coherently over 50 steps (R3 failure); two
                    // leave ~2e-6 unbiased-scale error.
                    FMA2(tN, nd, y, ONE2);                   // 1 - d*y
                    FMA2(y, y, tN, y);
                    FMA2(tN, nd, y, ONE2);
                    FMA2(y, y, tN, y);
                    u64 u_; MUL2(u_, m2[p], y);              // m'/(s+E)
                    FMA2(mu2[p], nA2, u_, mu2[p]);           // mu -= A * u
                }
            } else {
                // inactive hinge: G = 0 (kept for exactness; never taken here)
#pragma unroll
                for (int p = 0; p < 8; p++) {
                    u64 Z = 0ull;
                    FMA2(m2[p], B1_2, m2[p], Z);
                    FMA2(v2[p], B2_2, v2[p], Z);
                    float vlo, vhi; unpk2(vlo, vhi, v2[p]);
                    float ndlo = nE - sqrt_approx(vlo);
                    float ndhi = nE - sqrt_approx(vhi);
                    u64 y = pk2i(0xFEF477D5u - __float_as_uint(ndlo),
                                 0xFEF477D5u - __float_as_uint(ndhi));
                    u64 nd = pk2(ndlo, ndhi);
                    u64 tN;
                    FMA2(tN, nd, y, ONE2);
                    FMA2(y, y, tN, y);
                    FMA2(tN, nd, y, ONE2);
                    FMA2(y, y, tN, y);
                    u64 u_; MUL2(u_, m2[p], y);
                    FMA2(mu2[p], nA2, u_, mu2[p]);
                }
            }
        }

        float4* orow = (float4*)(mu_out + (size_t)warp * DIM);
#pragma unroll
        for (int i = 0; i < 4; i++) {
            float4 a;
            unpk2(a.x, a.y, mu2[2 * i]);
            unpk2(a.z, a.w, mu2[2 * i + 1]);
            orow[lane + 32 * i] = a;
        }

        if (lane == 0) atomicAdd(&blk_loss, loss_val);
    }

    __syncthreads();
    if (threadIdx.x == 0) atomicAdd(&g_loss_accum, blk_loss);
}

__global__ void wm_finalize_kernel(float* __restrict__ out_loss) {
    out_loss[0] = g_loss_accum * (1.0f / 131072.0f);
}

extern "C" void kernel_launch(void* const* d_in, const int* in_sizes, int n_in,
                              void* d_out, int out_size) {
    const float* mu      = (const float*)d_in[0];
    const float* log_var = (const float*)d_in[1];
    const float* carrier = (const float*)d_in[2];

    const int n_elem = in_sizes[0];          // 131072 * 512
    const int nrows  = n_elem / DIM;

    float* out        = (float*)d_out;
    float* mu_out     = out;
    float* logvar_out = out + n_elem;
    float* loss_out   = out + 2 * (size_t)n_elem;

    wm_init_kernel<<<1, 1>>>();

    const int threads = 128;                 // 4 warps (rows) per block
    const int blocks  = (nrows * 32 + threads - 1) / threads;
    wm_kernel<<<blocks, threads>>>(mu, log_var, carrier, mu_out, logvar_out, nrows);

    wm_finalize_kernel<<<1, 1>>>(loss_out);
}

// round 6
// speedup vs baseline: 1.3386x; 1.0443x over previous
#include <cuda_runtime.h>
#include <cstdint>

#define DIM 512
#define NSTEP 50

typedef unsigned long long u64;

__device__ float g_loss_accum;
__device__ float2 g_ae[NSTEP + 1];   // per-step {A_t, E_t}

__device__ __forceinline__ float rsqrt_approx(float x) {
    float y; asm("rsqrt.approx.f32 %0, %1;" : "=f"(y) : "f"(x)); return y;
}
__device__ __forceinline__ float sqrt_approx(float x) {
    float y; asm("sqrt.approx.f32 %0, %1;" : "=f"(y) : "f"(x)); return y;
}
__device__ __forceinline__ u64 pk2(float lo, float hi) {
    u64 r; asm("mov.b64 %0, {%1,%2};" : "=l"(r) : "f"(lo), "f"(hi)); return r;
}
__device__ __forceinline__ void unpk2(float& lo, float& hi, u64 v) {
    asm("mov.b64 {%0,%1}, %2;" : "=f"(lo), "=f"(hi) : "l"(v));
}
__device__ __forceinline__ u64 pk2i(unsigned lo, unsigned hi) {
    u64 r; asm("mov.b64 %0, {%1,%2};" : "=l"(r) : "r"(lo), "r"(hi)); return r;
}
#define FMA2(d, a, b, c) asm("fma.rn.f32x2 %0, %1, %2, %3;" : "=l"(d) : "l"(a), "l"(b), "l"(c))
#define MUL2(d, a, b)    asm("mul.rn.f32x2 %0, %1, %2;"     : "=l"(d) : "l"(a), "l"(b))

// Init: zero loss accumulator; precompute per-step Adam scalars (fp64).
//   rescaled Adam: m' = m/(C1*S), v' = v/(C2*S^2), S = 1/B
//   ds = sqrt(C2/(1-B2^t)); A_t = LR*C1/((1-B1^t)*ds); E_t = (EPS/S)/ds
__global__ void wm_init_kernel() {
    g_loss_accum = 0.0f;
    double b1t = 1.0, b2t = 1.0;
    for (int t = 1; t <= NSTEP; ++t) {
        b1t *= 0.9;
        b2t *= 0.999;
        double ds = sqrt(0.001 / (1.0 - b2t));
        double A  = 0.01 * 0.1 / ((1.0 - b1t) * ds);
        double E  = (1e-8 * 131072.0) / ds;
        g_ae[t] = make_float2((float)A, (float)E);
    }
}

__global__ __launch_bounds__(128, 5) void wm_kernel(
    const float* __restrict__ mu_in,
    const float* __restrict__ logvar_in,
    const float* __restrict__ carrier,
    float* __restrict__ mu_out,
    float* __restrict__ logvar_out,
    int nrows)
{
    // Negated carrier in shared memory: identical for every row — frees 16
    // registers/thread so occupancy rises from 4 to ~6 warps/SMSP.
    __shared__ float4 s_cN[DIM / 4];   // 128 float4 = 512 floats, 2 KB
    __shared__ float blk_loss;

    {
        const float4 cv = ((const float4*)carrier)[threadIdx.x];
        s_cN[threadIdx.x] = make_float4(-cv.x, -cv.y, -cv.z, -cv.w);
        if (threadIdx.x == 0) blk_loss = 0.0f;
    }
    __syncthreads();

    const int warp = (blockIdx.x * blockDim.x + threadIdx.x) >> 5;
    const int lane = threadIdx.x & 31;

    const float B1 = 0.9f;
    const float B2 = 0.999f;

    // Packed per-lane state: 8 f32x2 pairs each = 16 floats/lane = 512/warp
    u64 mu2[8], m2[8], v2[8];

    if (warp < nrows) {
        const float4* mrow = (const float4*)(mu_in + (size_t)warp * DIM);
        const float4* lrow = (const float4*)(logvar_in + (size_t)warp * DIM);
        float4*       lout = (float4*)(logvar_out + (size_t)warp * DIM);

#pragma unroll
        for (int i = 0; i < 4; i++) {
            float4 a = mrow[lane + 32 * i];
            mu2[2 * i]     = pk2(a.x, a.y);
            mu2[2 * i + 1] = pk2(a.z, a.w);
            lout[lane + 32 * i] = lrow[lane + 32 * i];  // log_var passthrough
            m2[2 * i] = 0ull; m2[2 * i + 1] = 0ull;
            v2[2 * i] = 0ull; v2[2 * i + 1] = 0ull;
        }

        const u64 B1_2 = pk2(B1, B1);
        const u64 B2_2 = pk2(B2, B2);
        const u64 ONE2 = pk2(1.0f, 1.0f);

        float loss_val = 0.0f;

        // Initial dot/norm partial accumulation (later steps fuse this into
        // the update loop so each step opens directly with the reduction).
        u64 dpa = 0ull, npa = 0ull;
#pragma unroll
        for (int i = 0; i < 4; i++) {
            float4 c4 = s_cN[lane + 32 * i];
            u64 ca = pk2(c4.x, c4.y), cb = pk2(c4.z, c4.w);
            FMA2(dpa, mu2[2 * i],     ca, dpa);
            FMA2(dpa, mu2[2 * i + 1], cb, dpa);
            FMA2(npa, mu2[2 * i],     mu2[2 * i],     npa);
            FMA2(npa, mu2[2 * i + 1], mu2[2 * i + 1], npa);
        }

#pragma unroll 1
        for (int t = 1; t <= NSTEP; ++t) {
            const float2 ae = g_ae[t];
            const float A = ae.x, E = ae.y;
            const float nE = -E;

            float dl, dh, nl, nh;
            unpk2(dl, dh, dpa);
            unpk2(nl, nh, npa);
            float dpn = dl + dh, np = nl + nh;
#pragma unroll
            for (int off = 16; off; off >>= 1) {
                dpn += __shfl_xor_sync(0xffffffffu, dpn, off);
                np  += __shfl_xor_sync(0xffffffffu, np,  off);
            }

            const float rnorm = rsqrt_approx(np);        // 1/||mu||
            const float norm  = np * rnorm;              // ||mu||
            // COS_THETA == 1.0f in fp32; margin = norm - dot = norm + dpn.
            const float margin = norm + dpn;
            if (t == NSTEP) loss_val = fmaxf(margin, 0.0f);
            const bool active = margin > 0.0f;           // warp-uniform

            const u64 rn2 = pk2(rnorm, rnorm);
            const u64 nA2 = pk2(-A, -A);

            dpa = 0ull; npa = 0ull;

            if (active) {
#pragma unroll
                for (int i = 0; i < 4; i++) {
                    float4 c4 = s_cN[lane + 32 * i];
                    u64 cN[2] = { pk2(c4.x, c4.y), pk2(c4.z, c4.w) };
#pragma unroll
                    for (int q = 0; q < 2; q++) {
                        const int p = 2 * i + q;
                        u64 G;
                        FMA2(G, rn2, mu2[p], cN[q]);         // G = mu/||mu|| - c
                        FMA2(m2[p], B1_2, m2[p], G);          // m' = B1*m' + G
                        u64 gg; MUL2(gg, G, G);
                        FMA2(v2[p], B2_2, v2[p], gg);         // v' = B2*v' + G^2
                        float vlo, vhi; unpk2(vlo, vhi, v2[p]);
                        // nd = -(sqrt(v)+E) in ONE fadd; magic seed for 1/d
                        // from bits(nd): 0x7EF477D5-bits(d) == 0xFEF477D5-bits(nd)
                        float ndlo = nE - sqrt_approx(vlo);
                        float ndhi = nE - sqrt_approx(vhi);
                        u64 y = pk2i(0xFEF477D5u - __float_as_uint(ndlo),
                                     0xFEF477D5u - __float_as_uint(ndhi));
                        u64 nd = pk2(ndlo, ndhi);
                        u64 tN;
                        // TWO Newton steps (one leaves biased ~1.4e-3 err that
                        // compounds coherently over 50 steps — R3 failure)
                        FMA2(tN, nd, y, ONE2);
                        FMA2(y, y, tN, y);
                        FMA2(tN, nd, y, ONE2);
                        FMA2(y, y, tN, y);
                        u64 u_; MUL2(u_, m2[p], y);           // m'/(s+E)
                        FMA2(mu2[p], nA2, u_, mu2[p]);        // mu -= A * u
                        // fused accumulation for next step's reduction
                        FMA2(dpa, mu2[p], cN[q], dpa);
                        FMA2(npa, mu2[p], mu2[p], npa);
                    }
                }
            } else {
                // inactive hinge: G = 0 (kept for exactness; never taken here)
#pragma unroll
                for (int i = 0; i < 4; i++) {
                    float4 c4 = s_cN[lane + 32 * i];
                    u64 cN[2] = { pk2(c4.x, c4.y), pk2(c4.z, c4.w) };
#pragma unroll
                    for (int q = 0; q < 2; q++) {
                        const int p = 2 * i + q;
                        u64 Z = 0ull;
                        FMA2(m2[p], B1_2, m2[p], Z);
                        FMA2(v2[p], B2_2, v2[p], Z);
                        float vlo, vhi; unpk2(vlo, vhi, v2[p]);
                        float ndlo = nE - sqrt_approx(vlo);
                        float ndhi = nE - sqrt_approx(vhi);
                        u64 y = pk2i(0xFEF477D5u - __float_as_uint(ndlo),
                                     0xFEF477D5u - __float_as_uint(ndhi));
                        u64 nd = pk2(ndlo, ndhi);
                        u64 tN;
                        FMA2(tN, nd, y, ONE2);
                        FMA2(y, y, tN, y);
                        FMA2(tN, nd, y, ONE2);
                        FMA2(y, y, tN, y);
                        u64 u_; MUL2(u_, m2[p], y);
                        FMA2(mu2[p], nA2, u_, mu2[p]);
                        FMA2(dpa, mu2[p], cN[q], dpa);
                        FMA2(npa, mu2[p], mu2[p], npa);
                    }
                }
            }
        }

        float4* orow = (float4*)(mu_out + (size_t)warp * DIM);
#pragma unroll
        for (int i = 0; i < 4; i++) {
            float4 a;
            unpk2(a.x, a.y, mu2[2 * i]);
            unpk2(a.z, a.w, mu2[2 * i + 1]);
            orow[lane + 32 * i] = a;
        }

        if (lane == 0) atomicAdd(&blk_loss, loss_val);
    }

    __syncthreads();
    if (threadIdx.x == 0) atomicAdd(&g_loss_accum, blk_loss);
}

__global__ void wm_finalize_kernel(float* __restrict__ out_loss) {
    out_loss[0] = g_loss_accum * (1.0f / 131072.0f);
}

extern "C" void kernel_launch(void* const* d_in, const int* in_sizes, int n_in,
                              void* d_out, int out_size) {
    const float* mu      = (const float*)d_in[0];
    const float* log_var = (const float*)d_in[1];
    const float* carrier = (const float*)d_in[2];

    const int n_elem = in_sizes[0];          // 131072 * 512
    const int nrows  = n_elem / DIM;

    float* out        = (float*)d_out;
    float* mu_out     = out;
    float* logvar_out = out + n_elem;
    float* loss_out   = out + 2 * (size_t)n_elem;

    wm_init_kernel<<<1, 1>>>();

    const int threads = 128;                 // 4 warps (rows) per block
    const int blocks  = (nrows * 32 + threads - 1) / threads;
    wm_kernel<<<blocks, threads>>>(mu, log_var, carrier, mu_out, logvar_out, nrows);

    wm_finalize_kernel<<<1, 1>>>(loss_out);
}

// round 7
// speedup vs baseline: 1.4244x; 1.0641x over previous
#include <cuda_runtime.h>
#include <cstdint>

#define DIM 512
#define NSTEP 50

typedef unsigned long long u64;

__device__ float g_loss_accum;
__device__ float2 g_ae[NSTEP + 1];   // per-step {A_t, E_t}

__device__ __forceinline__ float rsqrt_approx(float x) {
    float y; asm("rsqrt.approx.f32 %0, %1;" : "=f"(y) : "f"(x)); return y;
}
__device__ __forceinline__ float sqrt_approx(float x) {
    float y; asm("sqrt.approx.f32 %0, %1;" : "=f"(y) : "f"(x)); return y;
}
__device__ __forceinline__ u64 pk2(float lo, float hi) {
    u64 r; asm("mov.b64 %0, {%1,%2};" : "=l"(r) : "f"(lo), "f"(hi)); return r;
}
__device__ __forceinline__ void unpk2(float& lo, float& hi, u64 v) {
    asm("mov.b64 {%0,%1}, %2;" : "=f"(lo), "=f"(hi) : "l"(v));
}
__device__ __forceinline__ u64 pk2i(unsigned lo, unsigned hi) {
    u64 r; asm("mov.b64 %0, {%1,%2};" : "=l"(r) : "r"(lo), "r"(hi)); return r;
}
#define FMA2(d, a, b, c) asm("fma.rn.f32x2 %0, %1, %2, %3;" : "=l"(d) : "l"(a), "l"(b), "l"(c))
#define MUL2(d, a, b)    asm("mul.rn.f32x2 %0, %1, %2;"     : "=l"(d) : "l"(a), "l"(b))
#define ADD2(d, a, b)    asm("add.rn.f32x2 %0, %1, %2;"     : "=l"(d) : "l"(a), "l"(b))

// Init: zero loss accumulator; precompute per-step Adam scalars (fp64),
// one thread per step (serial 1-thread version cost 71 us — 3.5% of runtime).
//   rescaled Adam: m' = m/(C1*S), v' = v/(C2*S^2), S = 1/B
//   ds = sqrt(C2/(1-B2^t)); A_t = LR*C1/((1-B1^t)*ds); E_t = (EPS/S)/ds
__global__ void wm_init_kernel() {
    const int t = threadIdx.x;
    if (t == 0) g_loss_accum = 0.0f;
    if (t >= 1 && t <= NSTEP) {
        double b1t = pow(0.9, (double)t);
        double b2t = pow(0.999, (double)t);
        double ds = sqrt(0.001 / (1.0 - b2t));
        double A  = 0.01 * 0.1 / ((1.0 - b1t) * ds);
        double E  = (1e-8 * 131072.0) / ds;
        g_ae[t] = make_float2((float)A, (float)E);
    }
}

__global__ __launch_bounds__(128, 5) void wm_kernel(
    const float* __restrict__ mu_in,
    const float* __restrict__ logvar_in,
    const float* __restrict__ carrier,
    float* __restrict__ mu_out,
    float* __restrict__ logvar_out,
    int nrows)
{
    // Negated carrier in shared memory: identical for every row.
    __shared__ float4 s_cN[DIM / 4];   // 2 KB
    __shared__ float blk_loss;

    {
        const float4 cv = ((const float4*)carrier)[threadIdx.x];
        s_cN[threadIdx.x] = make_float4(-cv.x, -cv.y, -cv.z, -cv.w);
        if (threadIdx.x == 0) blk_loss = 0.0f;
    }
    __syncthreads();

    const int warp = (blockIdx.x * blockDim.x + threadIdx.x) >> 5;
    const int lane = threadIdx.x & 31;

    const float B1 = 0.9f;
    const float B2 = 0.999f;

    // Packed per-lane state: 8 f32x2 pairs each = 16 floats/lane = 512/warp
    u64 mu2[8], m2[8], v2[8];

    if (warp < nrows) {
        const float4* mrow = (const float4*)(mu_in + (size_t)warp * DIM);
        const float4* lrow = (const float4*)(logvar_in + (size_t)warp * DIM);
        float4*       lout = (float4*)(logvar_out + (size_t)warp * DIM);

#pragma unroll
        for (int i = 0; i < 4; i++) {
            float4 a = mrow[lane + 32 * i];
            mu2[2 * i]     = pk2(a.x, a.y);
            mu2[2 * i + 1] = pk2(a.z, a.w);
            lout[lane + 32 * i] = lrow[lane + 32 * i];  // log_var passthrough
            m2[2 * i] = 0ull; m2[2 * i + 1] = 0ull;
            v2[2 * i] = 0ull; v2[2 * i + 1] = 0ull;
        }

        const u64 B1_2 = pk2(B1, B1);
        const u64 B2_2 = pk2(B2, B2);
        const u64 ONE2 = pk2(1.0f, 1.0f);
        const u64 NEG1_2 = pk2(-1.0f, -1.0f);

        float loss_val = 0.0f;

        // Initial dot/norm partial accumulation (later steps fuse this into
        // the update loop so each step opens directly with the reduction).
        u64 dpa = 0ull, npa = 0ull;
#pragma unroll
        for (int i = 0; i < 4; i++) {
            float4 c4 = s_cN[lane + 32 * i];
            u64 ca = pk2(c4.x, c4.y), cb = pk2(c4.z, c4.w);
            FMA2(dpa, mu2[2 * i],     ca, dpa);
            FMA2(dpa, mu2[2 * i + 1], cb, dpa);
            FMA2(npa, mu2[2 * i],     mu2[2 * i],     npa);
            FMA2(npa, mu2[2 * i + 1], mu2[2 * i + 1], npa);
        }

#pragma unroll 1
        for (int t = 1; t <= NSTEP; ++t) {
            const float2 ae = g_ae[t];
            const float A = ae.x, E = ae.y;

            // Horizontal within-pair combine, then packed butterfly on the
            // {dpn, np} pair: 2 SHFL + 1 add.f32x2 per stage.
            float dl, dh, nl, nh;
            unpk2(dl, dh, dpa);
            unpk2(nl, nh, npa);
            u64 red = pk2(dl + dh, nl + nh);
#pragma unroll
            for (int off = 16; off; off >>= 1) {
                unsigned rlo = (unsigned)red, rhi = (unsigned)(red >> 32);
                unsigned slo = __shfl_xor_sync(0xffffffffu, rlo, off);
                unsigned shi = __shfl_xor_sync(0xffffffffu, rhi, off);
                u64 other = pk2i(slo, shi);
                ADD2(red, red, other);
            }
            float dpn, np;
            unpk2(dpn, np, red);    // dpn = -(mu.c), np = ||mu||^2

            const float rnorm = rsqrt_approx(np);        // 1/||mu||
            const float norm  = np * rnorm;              // ||mu||
            // COS_THETA == 1.0f in fp32; margin = norm - dot = norm + dpn.
            const float margin = norm + dpn;
            if (t == NSTEP) loss_val = fmaxf(margin, 0.0f);
            const bool active = margin > 0.0f;           // warp-uniform

            const u64 rn2  = pk2(rnorm, rnorm);
            const u64 nA2  = pk2(-A, -A);
            const u64 nEE2 = pk2(-E, -E);

            dpa = 0ull; npa = 0ull;

            if (active) {
#pragma unroll
                for (int i = 0; i < 4; i++) {
                    float4 c4 = s_cN[lane + 32 * i];
                    u64 cN[2] = { pk2(c4.x, c4.y), pk2(c4.z, c4.w) };
#pragma unroll
                    for (int q = 0; q < 2; q++) {
                        const int p = 2 * i + q;
                        u64 G;
                        FMA2(G, rn2, mu2[p], cN[q]);         // G = mu/||mu|| - c
                        FMA2(m2[p], B1_2, m2[p], G);          // m' = B1*m' + G
                        u64 gg; MUL2(gg, G, G);
                        FMA2(v2[p], B2_2, v2[p], gg);         // v' = B2*v' + G^2
                        float vlo, vhi; unpk2(vlo, vhi, v2[p]);
                        u64 s2 = pk2(sqrt_approx(vlo), sqrt_approx(vhi));
                        // nd = -(s+E) in ONE packed FMA2; magic seed for 1/d
                        // from bits(nd): 0x7EF477D5-bits(d) == 0xFEF477D5-bits(nd)
                        u64 nd; FMA2(nd, s2, NEG1_2, nEE2);
                        float ndlo, ndhi; unpk2(ndlo, ndhi, nd);
                        u64 y = pk2i(0xFEF477D5u - __float_as_uint(ndlo),
                                     0xFEF477D5u - __float_as_uint(ndhi));
                        u64 tN;
                        // TWO Newton steps (one leaves biased ~1.4e-3 err that
                        // compounds coherently over 50 steps — R3 failure)
                        FMA2(tN, nd, y, ONE2);
                        FMA2(y, y, tN, y);
                        FMA2(tN, nd, y, ONE2);
                        FMA2(y, y, tN, y);
                        u64 u_; MUL2(u_, m2[p], y);           // m'/(s+E)
                        FMA2(mu2[p], nA2, u_, mu2[p]);        // mu -= A * u
                        // fused accumulation for next step's reduction
                        FMA2(dpa, mu2[p], cN[q], dpa);
                        FMA2(npa, mu2[p], mu2[p], npa);
                    }
                }
            } else {
                // inactive hinge: G = 0 (kept for exactness; never taken here)
#pragma unroll
                for (int i = 0; i < 4; i++) {
                    float4 c4 = s_cN[lane + 32 * i];
                    u64 cN[2] = { pk2(c4.x, c4.y), pk2(c4.z, c4.w) };
#pragma unroll
                    for (int q = 0; q < 2; q++) {
                        const int p = 2 * i + q;
                        u64 Z = 0ull;
                        FMA2(m2[p], B1_2, m2[p], Z);
                        FMA2(v2[p], B2_2, v2[p], Z);
                        float vlo, vhi; unpk2(vlo, vhi, v2[p]);
                        u64 s2 = pk2(sqrt_approx(vlo), sqrt_approx(vhi));
                        u64 nd; FMA2(nd, s2, NEG1_2, nEE2);
                        float ndlo, ndhi; unpk2(ndlo, ndhi, nd);
                        u64 y = pk2i(0xFEF477D5u - __float_as_uint(ndlo),
                                     0xFEF477D5u - __float_as_uint(ndhi));
                        u64 tN;
                        FMA2(tN, nd, y, ONE2);
                        FMA2(y, y, tN, y);
                        FMA2(tN, nd, y, ONE2);
                        FMA2(y, y, tN, y);
                        u64 u_; MUL2(u_, m2[p], y);
                        FMA2(mu2[p], nA2, u_, mu2[p]);
                        FMA2(dpa, mu2[p], cN[q], dpa);
                        FMA2(npa, mu2[p], mu2[p], npa);
                    }
                }
            }
        }

        float4* orow = (float4*)(mu_out + (size_t)warp * DIM);
#pragma unroll
        for (int i = 0; i < 4; i++) {
            float4 a;
            unpk2(a.x, a.y, mu2[2 * i]);
            unpk2(a.z, a.w, mu2[2 * i + 1]);
            orow[lane + 32 * i] = a;
        }

        if (lane == 0) atomicAdd(&blk_loss, loss_val);
    }

    __syncthreads();
    if (threadIdx.x == 0) atomicAdd(&g_loss_accum, blk_loss);
}

__global__ void wm_finalize_kernel(float* __restrict__ out_loss) {
    out_loss[0] = g_loss_accum * (1.0f / 131072.0f);
}

extern "C" void kernel_launch(void* const* d_in, const int* in_sizes, int n_in,
                              void* d_out, int out_size) {
    const float* mu      = (const float*)d_in[0];
    const float* log_var = (const float*)d_in[1];
    const float* carrier = (const float*)d_in[2];

    const int n_elem = in_sizes[0];          // 131072 * 512
    const int nrows  = n_elem / DIM;

    float* out        = (float*)d_out;
    float* mu_out     = out;
    float* logvar_out = out + n_elem;
    float* loss_out   = out + 2 * (size_t)n_elem;

    wm_init_kernel<<<1, 64>>>();

    const int threads = 128;                 // 4 warps (rows) per block
    const int blocks  = (nrows * 32 + threads - 1) / threads;
    wm_kernel<<<blocks, threads>>>(mu, log_var, carrier, mu_out, logvar_out, nrows);

    wm_finalize_kernel<<<1, 1>>>(loss_out);
}

// round 8
// speedup vs baseline: 1.4683x; 1.0309x over previous
#include <cuda_runtime.h>
#include <cstdint>

#define DIM 512
#define NSTEP 50

typedef unsigned long long u64;

__device__ float g_loss_accum;
__device__ float2 g_ae[NSTEP + 1];   // per-step {A_t, E_t}

__device__ __forceinline__ float rsqrt_approx(float x) {
    float y; asm("rsqrt.approx.f32 %0, %1;" : "=f"(y) : "f"(x)); return y;
}
__device__ __forceinline__ float sqrt_approx(float x) {
    float y; asm("sqrt.approx.f32 %0, %1;" : "=f"(y) : "f"(x)); return y;
}
__device__ __forceinline__ u64 pk2(float lo, float hi) {
    u64 r; asm("mov.b64 %0, {%1,%2};" : "=l"(r) : "f"(lo), "f"(hi)); return r;
}
__device__ __forceinline__ void unpk2(float& lo, float& hi, u64 v) {
    asm("mov.b64 {%0,%1}, %2;" : "=f"(lo), "=f"(hi) : "l"(v));
}
__device__ __forceinline__ u64 pk2i(unsigned lo, unsigned hi) {
    u64 r; asm("mov.b64 %0, {%1,%2};" : "=l"(r) : "r"(lo), "r"(hi)); return r;
}
#define FMA2(d, a, b, c) asm("fma.rn.f32x2 %0, %1, %2, %3;" : "=l"(d) : "l"(a), "l"(b), "l"(c))
#define MUL2(d, a, b)    asm("mul.rn.f32x2 %0, %1, %2;"     : "=l"(d) : "l"(a), "l"(b))
#define ADD2(d, a, b)    asm("add.rn.f32x2 %0, %1, %2;"     : "=l"(d) : "l"(a), "l"(b))

// Init: zero loss accumulator; precompute per-step Adam scalars (fp64),
// one thread per step.
//   rescaled Adam: m' = m/(C1*S), v' = v/(C2*S^2), S = 1/B
//   ds = sqrt(C2/(1-B2^t)); A_t = LR*C1/((1-B1^t)*ds); E_t = (EPS/S)/ds
__global__ void wm_init_kernel() {
    const int t = threadIdx.x;
    if (t == 0) g_loss_accum = 0.0f;
    if (t >= 1 && t <= NSTEP) {
        double b1t = pow(0.9, (double)t);
        double b2t = pow(0.999, (double)t);
        double ds = sqrt(0.001 / (1.0 - b2t));
        double A  = 0.01 * 0.1 / ((1.0 - b1t) * ds);
        double E  = (1e-8 * 131072.0) / ds;
        g_ae[t] = make_float2((float)A, (float)E);
    }
}

__global__ __launch_bounds__(128, 5) void wm_kernel(
    const float* __restrict__ mu_in,
    const float* __restrict__ logvar_in,
    const float* __restrict__ carrier,
    float* __restrict__ mu_out,
    float* __restrict__ logvar_out,
    int nrows)
{
    // Negated carrier in shared memory: identical for every row.
    __shared__ float4 s_cN[DIM / 4];   // 2 KB
    __shared__ float blk_loss;

    {
        const float4 cv = ((const float4*)carrier)[threadIdx.x];
        s_cN[threadIdx.x] = make_float4(-cv.x, -cv.y, -cv.z, -cv.w);
        if (threadIdx.x == 0) blk_loss = 0.0f;
    }
    __syncthreads();

    const int warp = (blockIdx.x * blockDim.x + threadIdx.x) >> 5;
    const int lane = threadIdx.x & 31;

    const float B1 = 0.9f;
    const float B2 = 0.999f;

    // Packed per-lane state: 8 f32x2 pairs each = 16 floats/lane = 512/warp
    u64 mu2[8], m2[8], v2[8];

    if (warp < nrows) {
        const float4* mrow = (const float4*)(mu_in + (size_t)warp * DIM);
        const float4* lrow = (const float4*)(logvar_in + (size_t)warp * DIM);
        float4*       lout = (float4*)(logvar_out + (size_t)warp * DIM);

#pragma unroll
        for (int i = 0; i < 4; i++) {
            float4 a = mrow[lane + 32 * i];
            mu2[2 * i]     = pk2(a.x, a.y);
            mu2[2 * i + 1] = pk2(a.z, a.w);
            lout[lane + 32 * i] = lrow[lane + 32 * i];  // log_var passthrough
            m2[2 * i] = 0ull; m2[2 * i + 1] = 0ull;
            v2[2 * i] = 0ull; v2[2 * i + 1] = 0ull;
        }

        const u64 B1_2 = pk2(B1, B1);
        const u64 B2_2 = pk2(B2, B2);
        const u64 ONE2 = pk2(1.0f, 1.0f);
        const u64 NEG1_2 = pk2(-1.0f, -1.0f);

        float loss_val = 0.0f;

        // Initial dot/norm partial accumulation (later steps fuse this into
        // the update loop so each step opens directly with the reduction).
        u64 dpa = 0ull, npa = 0ull;
#pragma unroll
        for (int i = 0; i < 4; i++) {
            float4 c4 = s_cN[lane + 32 * i];
            u64 ca = pk2(c4.x, c4.y), cb = pk2(c4.z, c4.w);
            FMA2(dpa, mu2[2 * i],     ca, dpa);
            FMA2(dpa, mu2[2 * i + 1], cb, dpa);
            FMA2(npa, mu2[2 * i],     mu2[2 * i],     npa);
            FMA2(npa, mu2[2 * i + 1], mu2[2 * i + 1], npa);
        }

#pragma unroll 1
        for (int t = 1; t <= NSTEP; ++t) {
            const float2 ae = g_ae[t];
            const float A = ae.x, E = ae.y;

            // Horizontal within-pair combine, then packed butterfly on the
            // {dpn, np} pair: 2 SHFL + 1 add.f32x2 per stage.
            float dl, dh, nl, nh;
            unpk2(dl, dh, dpa);
            unpk2(nl, nh, npa);
            u64 red = pk2(dl + dh, nl + nh);
#pragma unroll
            for (int off = 16; off; off >>= 1) {
                unsigned rlo = (unsigned)red, rhi = (unsigned)(red >> 32);
                unsigned slo = __shfl_xor_sync(0xffffffffu, rlo, off);
                unsigned shi = __shfl_xor_sync(0xffffffffu, rhi, off);
                u64 other = pk2i(slo, shi);
                ADD2(red, red, other);
            }
            float dpn, np;
            unpk2(dpn, np, red);    // dpn = -(mu.c), np = ||mu||^2

            const float rnorm = rsqrt_approx(np);        // 1/||mu||
            const float norm  = np * rnorm;              // ||mu||
            // COS_THETA == 1.0f in fp32; margin = norm - dot = norm + dpn.
            const float margin = norm + dpn;
            if (t == NSTEP) loss_val = fmaxf(margin, 0.0f);
            const bool active = margin > 0.0f;           // warp-uniform

            const u64 rn2  = pk2(rnorm, rnorm);
            const u64 nA2  = pk2(-A, -A);
            const u64 nEE2 = pk2(-E, -E);

            dpa = 0ull; npa = 0ull;

            if (active) {
#pragma unroll
                for (int i = 0; i < 4; i++) {
                    float4 c4 = s_cN[lane + 32 * i];
                    u64 cN[2] = { pk2(c4.x, c4.y), pk2(c4.z, c4.w) };
#pragma unroll
                    for (int q = 0; q < 2; q++) {
                        const int p = 2 * i + q;
                        u64 G;
                        FMA2(G, rn2, mu2[p], cN[q]);         // G = mu/||mu|| - c
                        FMA2(m2[p], B1_2, m2[p], G);          // m' = B1*m' + G
                        u64 gg; MUL2(gg, G, G);
                        FMA2(v2[p], B2_2, v2[p], gg);         // v' = B2*v' + G^2
                        float vlo, vhi; unpk2(vlo, vhi, v2[p]);
                        u64 s2 = pk2(sqrt_approx(vlo), sqrt_approx(vhi));
                        // nd = -(s+E) in one packed FMA2; magic seed for 1/d
                        // from bits(nd): 0x7EF477D5-bits(d) == 0xFEF477D5-bits(nd)
                        u64 nd; FMA2(nd, s2, NEG1_2, nEE2);
                        float ndlo, ndhi; unpk2(ndlo, ndhi, nd);
                        u64 y = pk2i(0xFEF477D5u - __float_as_uint(ndlo),
                                     0xFEF477D5u - __float_as_uint(ndhi));
                        // HALLEY (cubic): rel-err -e^3 in [-4e-5, 4e-5],
                        // sign-oscillating with mantissa (no coherent bias,
                        // unlike 1-Newton's strictly-negative error — R3).
                        // Fold -A into the final correction:
                        //   w = -A*y0*(1 + e + e^2) = -A/(s+E) * (1 + O(e^3))
                        u64 e;  FMA2(e, nd, y, ONE2);         // e = 1 - d*y0
                        u64 e2; FMA2(e2, e, e, e);            // e + e^2
                        u64 w;  MUL2(w, nA2, y);              // -A*y0
                        FMA2(w, w, e2, w);                    // w *= (1+e+e^2)
                        FMA2(mu2[p], w, m2[p], mu2[p]);       // mu += w*m
                        // fused accumulation for next step's reduction
                        FMA2(dpa, mu2[p], cN[q], dpa);
                        FMA2(npa, mu2[p], mu2[p], npa);
                    }
                }
            } else {
                // inactive hinge: G = 0 (kept for exactness; never taken here)
#pragma unroll
                for (int i = 0; i < 4; i++) {
                    float4 c4 = s_cN[lane + 32 * i];
                    u64 cN[2] = { pk2(c4.x, c4.y), pk2(c4.z, c4.w) };
#pragma unroll
                    for (int q = 0; q < 2; q++) {
                        const int p = 2 * i + q;
                        u64 Z = 0ull;
                        FMA2(m2[p], B1_2, m2[p], Z);
                        FMA2(v2[p], B2_2, v2[p], Z);
                        float vlo, vhi; unpk2(vlo, vhi, v2[p]);
                        u64 s2 = pk2(sqrt_approx(vlo), sqrt_approx(vhi));
                        u64 nd; FMA2(nd, s2, NEG1_2, nEE2);
                        float ndlo, ndhi; unpk2(ndlo, ndhi, nd);
                        u64 y = pk2i(0xFEF477D5u - __float_as_uint(ndlo),
                                     0xFEF477D5u - __float_as_uint(ndhi));
                        u64 e;  FMA2(e, nd, y, ONE2);
                        u64 e2; FMA2(e2, e, e, e);
                        u64 w;  MUL2(w, nA2, y);
                        FMA2(w, w, e2, w);
                        FMA2(mu2[p], w, m2[p], mu2[p]);
                        FMA2(dpa, mu2[p], cN[q], dpa);
                        FMA2(npa, mu2[p], mu2[p], npa);
                    }
                }
            }
        }

        float4* orow = (float4*)(mu_out + (size_t)warp * DIM);
#pragma unroll
        for (int i = 0; i < 4; i++) {
            float4 a;
            unpk2(a.x, a.y, mu2[2 * i]);
            unpk2(a.z, a.w, mu2[2 * i + 1]);
            orow[lane + 32 * i] = a;
        }

        if (lane == 0) atomicAdd(&blk_loss, loss_val);
    }

    __syncthreads();
    if (threadIdx.x == 0) atomicAdd(&g_loss_accum, blk_loss);
}

__global__ void wm_finalize_kernel(float* __restrict__ out_loss) {
    out_loss[0] = g_loss_accum * (1.0f / 131072.0f);
}

extern "C" void kernel_launch(void* const* d_in, const int* in_sizes, int n_in,
                              void* d_out, int out_size) {
    const float* mu      = (const float*)d_in[0];
    const float* log_var = (const float*)d_in[1];
    const float* carrier = (const float*)d_in[2];

    const int n_elem = in_sizes[0];          // 131072 * 512
    const int nrows  = n_elem / DIM;

    float* out        = (float*)d_out;
    float* mu_out     = out;
    float* logvar_out = out + n_elem;
    float* loss_out   = out + 2 * (size_t)n_elem;

    wm_init_kernel<<<1, 64>>>();

    const int threads = 128;                 // 4 warps (rows) per block
    const int blocks  = (nrows * 32 + threads - 1) / threads;
    wm_kernel<<<blocks, threads>>>(mu, log_var, carrier, mu_out, logvar_out, nrows);

    wm_finalize_kernel<<<1, 1>>>(loss_out);
}